// round 17
// baseline (speedup 1.0000x reference)
#include <cuda_runtime.h>
#include <cuda_bf16.h>
#include <cstdint>

// out[b,c] = H @ x[b,c] @ H^T for 65536 independent 32x32 fp32 matrices.
// mma.sync bf16 path, hi/lo split (3 cross terms), fp32 accumulation,
// DCT even/odd butterfly in BOTH stages (24+24 MMAs), in-register
// movmatrix handoff, permutations undone in the store epilogue.
// R16: 2 matrices per warp, software pipelined:
//  - batch-1 L2-prefetched at kernel start (no registers held),
//  - batch-1 LDGs issued right after batch-0's stage-1 MMAs so DRAM
//    latency hides behind batch-0 handoff + stage 2 + store,
//  - H staging / syncthreads / stage-2 A-frags amortized over 2 matrices.

#define NTHREADS 128
#define EPITCH 24                // He/Ho table pitch in bf16 (conflict-free)

__device__ __forceinline__ uint32_t lds32(const unsigned short* p) {
    return *reinterpret_cast<const uint32_t*>(p);
}

__device__ __forceinline__ uint32_t pack_bf16x2(float hi, float lo) {
    uint32_t r;
    asm("cvt.rn.bf16x2.f32 %0, %1, %2;" : "=r"(r) : "f"(hi), "f"(lo));
    return r;
}
__device__ __forceinline__ float bf16lo_f(uint32_t p) {
    return __uint_as_float(p << 16);
}
__device__ __forceinline__ float bf16hi_f(uint32_t p) {
    return __uint_as_float(p & 0xFFFF0000u);
}
// split two f32 (v0=k, v1=k+1) into packed bf16x2 hi + residual lo
__device__ __forceinline__ void split2(float v0, float v1,
                                       uint32_t& h, uint32_t& l) {
    h = pack_bf16x2(v1, v0);
    l = pack_bf16x2(v1 - bf16hi_f(h), v0 - bf16lo_f(h));
}

__device__ __forceinline__ uint32_t movm_t(uint32_t a) {
    uint32_t d;
    asm volatile("movmatrix.sync.aligned.m8n8.trans.b16 %0, %1;"
                 : "=r"(d) : "r"(a));
    return d;
}

__device__ __forceinline__ void mma16816(float* d, const uint32_t* a,
                                         uint32_t b0, uint32_t b1) {
    asm("mma.sync.aligned.m16n8k16.row.col.f32.bf16.bf16.f32 "
        "{%0,%1,%2,%3}, {%4,%5,%6,%7}, {%8,%9}, {%0,%1,%2,%3};"
        : "+f"(d[0]), "+f"(d[1]), "+f"(d[2]), "+f"(d[3])
        : "r"(a[0]), "r"(a[1]), "r"(a[2]), "r"(a[3]), "r"(b0), "r"(b1));
}

__global__ __launch_bounds__(NTHREADS, 5)
void dct2d_mma_kernel(const float* __restrict__ x,
                      const float* __restrict__ H,
                      float* __restrict__ out,
                      int nMat)
{
    __shared__ __align__(16) unsigned short Heh[16 * EPITCH];
    __shared__ __align__(16) unsigned short Hel[16 * EPITCH];
    __shared__ __align__(16) unsigned short Hoh[16 * EPITCH];
    __shared__ __align__(16) unsigned short Hol[16 * EPITCH];

    const int tid  = threadIdx.x;
    const int w    = tid >> 5;
    const int lane = tid & 31;
    const int g    = lane >> 2;   // mma groupID 0..7
    const int t    = lane & 3;    // thread-in-group 0..3

    const size_t m0 = (size_t)blockIdx.x * 8 + w;  // this warp: m0 and m0+4
    const float* __restrict__ Xw0 = x + m0 * 1024;
    const float* __restrict__ Xw1 = Xw0 + 4 * 1024;

    // ---- issue batch-0 X loads FIRST ----
    float2 v0[2][2], v1[2][2], p0[2][2], p1[2][2];
    #pragma unroll
    for (int mi = 0; mi < 2; mi++)
        #pragma unroll
        for (int rh = 0; rh < 2; rh++) {
            const float* rp = Xw0 + (16 * mi + 8 * rh + g) * 32;
            v0[mi][rh] = *reinterpret_cast<const float2*>(rp + 2 * t);
            v1[mi][rh] = *reinterpret_cast<const float2*>(rp + 8 + 2 * t);
            p0[mi][rh] = *reinterpret_cast<const float2*>(rp + 30 - 2 * t);
            p1[mi][rh] = *reinterpret_cast<const float2*>(rp + 22 - 2 * t);
        }

    // ---- L2 prefetch for batch 1: one 128B line per lane (4KB total) ----
    asm volatile("prefetch.global.L2 [%0];" :: "l"(Xw1 + lane * 32));

    // ---- stage the even/odd half-K H tables (only k<16 needed anywhere) ----
    #pragma unroll
    for (int e = tid; e < 512; e += NTHREADS) {
        int r = e >> 4;          // H row 0..31
        int c = e & 15;          // H col 0..15
        float v = H[r * 32 + c];
        __nv_bfloat16 hb = __float2bfloat16_rn(v);
        unsigned short hh = __bfloat16_as_ushort(hb);
        unsigned short hl =
            __bfloat16_as_ushort(__float2bfloat16_rn(v - __bfloat162float(hb)));
        int hr = r >> 1;
        if (r & 1) { Hoh[hr * EPITCH + c] = hh; Hol[hr * EPITCH + c] = hl; }
        else       { Heh[hr * EPITCH + c] = hh; Hel[hr * EPITCH + c] = hl; }
    }
    __syncthreads();

    // ---- stage-2 A frags (He/Ho), hoisted: shared by both batches ----
    uint32_t A2eh[4], A2el[4], A2oh[4], A2ol[4];
    {
        int off = g * EPITCH + 2 * t;
        A2eh[0] = lds32(Heh + off);
        A2eh[1] = lds32(Heh + off + 8 * EPITCH);
        A2eh[2] = lds32(Heh + off + 8);
        A2eh[3] = lds32(Heh + off + 8 * EPITCH + 8);
        A2el[0] = lds32(Hel + off);
        A2el[1] = lds32(Hel + off + 8 * EPITCH);
        A2el[2] = lds32(Hel + off + 8);
        A2el[3] = lds32(Hel + off + 8 * EPITCH + 8);
        A2oh[0] = lds32(Hoh + off);
        A2oh[1] = lds32(Hoh + off + 8 * EPITCH);
        A2oh[2] = lds32(Hoh + off + 8);
        A2oh[3] = lds32(Hoh + off + 8 * EPITCH + 8);
        A2ol[0] = lds32(Hol + off);
        A2ol[1] = lds32(Hol + off + 8 * EPITCH);
        A2ol[2] = lds32(Hol + off + 8);
        A2ol[3] = lds32(Hol + off + 8 * EPITCH + 8);
    }

    #pragma unroll
    for (int b = 0; b < 2; b++) {
        // ---- stage-1 B frags (reloaded per batch: caps register lifetime) ----
        uint32_t Beh[2][2], Bel[2][2], Boh[2][2], Bol[2][2];
        #pragma unroll
        for (int ni = 0; ni < 2; ni++) {
            int off = (8 * ni + g) * EPITCH + 2 * t;
            Beh[ni][0] = lds32(Heh + off);  Beh[ni][1] = lds32(Heh + off + 8);
            Bel[ni][0] = lds32(Hel + off);  Bel[ni][1] = lds32(Hel + off + 8);
            Boh[ni][0] = lds32(Hoh + off);  Boh[ni][1] = lds32(Hoh + off + 8);
            Bol[ni][0] = lds32(Hol + off);  Bol[ni][1] = lds32(Hol + off + 8);
        }

        // ---- butterfly E/O in registers + split to stage-1 A frags ----
        uint32_t Aeh[2][4], Ael[2][4], Aoh[2][4], Aol[2][4];
        #pragma unroll
        for (int mi = 0; mi < 2; mi++)
            #pragma unroll
            for (int rh = 0; rh < 2; rh++) {
                float2 a = v0[mi][rh], bb = p0[mi][rh];
                float2 c = v1[mi][rh], d = p1[mi][rh];
                float e0 = a.x + bb.y, e1 = a.y + bb.x;
                float o0 = a.x - bb.y, o1 = a.y - bb.x;
                float e2 = c.x + d.y,  e3 = c.y + d.x;
                float o2 = c.x - d.y,  o3 = c.y - d.x;
                split2(e0, e1, Aeh[mi][rh],     Ael[mi][rh]);
                split2(e2, e3, Aeh[mi][2 + rh], Ael[mi][2 + rh]);
                split2(o0, o1, Aoh[mi][rh],     Aol[mi][rh]);
                split2(o2, o3, Aoh[mi][2 + rh], Aol[mi][2 + rh]);
            }

        // ============ stage 1: Utilde = [E@He^T | O@Ho^T] (24 MMAs) ========
        float acc[2][4][4];
        #pragma unroll
        for (int mi = 0; mi < 2; mi++)
            #pragma unroll
            for (int ni = 0; ni < 4; ni++)
                #pragma unroll
                for (int r = 0; r < 4; r++) acc[mi][ni][r] = 0.0f;

        #pragma unroll
        for (int ni = 0; ni < 2; ni++) {
            #pragma unroll
            for (int mi = 0; mi < 2; mi++) mma16816(acc[mi][ni],     Aeh[mi], Beh[ni][0], Beh[ni][1]);
            #pragma unroll
            for (int mi = 0; mi < 2; mi++) mma16816(acc[mi][2 + ni], Aoh[mi], Boh[ni][0], Boh[ni][1]);
            #pragma unroll
            for (int mi = 0; mi < 2; mi++) mma16816(acc[mi][ni],     Aeh[mi], Bel[ni][0], Bel[ni][1]);
            #pragma unroll
            for (int mi = 0; mi < 2; mi++) mma16816(acc[mi][2 + ni], Aoh[mi], Bol[ni][0], Bol[ni][1]);
            #pragma unroll
            for (int mi = 0; mi < 2; mi++) mma16816(acc[mi][ni],     Ael[mi], Beh[ni][0], Beh[ni][1]);
            #pragma unroll
            for (int mi = 0; mi < 2; mi++) mma16816(acc[mi][2 + ni], Aol[mi], Boh[ni][0], Boh[ni][1]);
        }

        // ---- issue batch-1 X loads NOW (batch-0 A frags just died; the
        //      DRAM/L2 latency hides behind handoff + stage 2 + store) ----
        if (b == 0) {
            #pragma unroll
            for (int mi = 0; mi < 2; mi++)
                #pragma unroll
                for (int rh = 0; rh < 2; rh++) {
                    const float* rp = Xw1 + (16 * mi + 8 * rh + g) * 32;
                    v0[mi][rh] = *reinterpret_cast<const float2*>(rp + 2 * t);
                    v1[mi][rh] = *reinterpret_cast<const float2*>(rp + 8 + 2 * t);
                    p0[mi][rh] = *reinterpret_cast<const float2*>(rp + 30 - 2 * t);
                    p1[mi][rh] = *reinterpret_cast<const float2*>(rp + 22 - 2 * t);
                }
        }

        // ---- stage-2 butterfly: E2/O2[i] = U[i] +/- U[31-i] (shfl.xor 28) --
        float e2[4][4], o2[4][4];
        #pragma unroll
        for (int ni = 0; ni < 4; ni++) {
            float s0 = __shfl_xor_sync(0xffffffffu, acc[1][ni][0], 28);
            float s1 = __shfl_xor_sync(0xffffffffu, acc[1][ni][1], 28);
            float s2 = __shfl_xor_sync(0xffffffffu, acc[1][ni][2], 28);
            float s3 = __shfl_xor_sync(0xffffffffu, acc[1][ni][3], 28);
            e2[ni][0] = acc[0][ni][0] + s2;  o2[ni][0] = acc[0][ni][0] - s2;
            e2[ni][1] = acc[0][ni][1] + s3;  o2[ni][1] = acc[0][ni][1] - s3;
            e2[ni][2] = acc[0][ni][2] + s0;  o2[ni][2] = acc[0][ni][2] - s0;
            e2[ni][3] = acc[0][ni][3] + s1;  o2[ni][3] = acc[0][ni][3] - s1;
        }

        // ---- handoff: split + in-register transpose ----
        uint32_t Be2h[4][2], Be2l[4][2], Bo2h[4][2], Bo2l[4][2];
        #pragma unroll
        for (int ni = 0; ni < 4; ni++) {
            uint32_t h01, l01, h23, l23;
            split2(e2[ni][0], e2[ni][1], h01, l01);
            split2(e2[ni][2], e2[ni][3], h23, l23);
            Be2h[ni][0] = movm_t(h01);  Be2h[ni][1] = movm_t(h23);
            Be2l[ni][0] = movm_t(l01);  Be2l[ni][1] = movm_t(l23);
            split2(o2[ni][0], o2[ni][1], h01, l01);
            split2(o2[ni][2], o2[ni][3], h23, l23);
            Bo2h[ni][0] = movm_t(h01);  Bo2h[ni][1] = movm_t(h23);
            Bo2l[ni][0] = movm_t(l01);  Bo2l[ni][1] = movm_t(l23);
        }

        // ===== stage 2: out_even = He@E2, out_odd = Ho@O2 (24 MMAs) ========
        float ae[4][4], ao[4][4];
        #pragma unroll
        for (int ni = 0; ni < 4; ni++)
            #pragma unroll
            for (int r = 0; r < 4; r++) { ae[ni][r] = 0.0f; ao[ni][r] = 0.0f; }

        #pragma unroll
        for (int ni = 0; ni < 4; ni++) {
            mma16816(ae[ni], A2eh, Be2h[ni][0], Be2h[ni][1]);
            mma16816(ao[ni], A2oh, Bo2h[ni][0], Bo2h[ni][1]);
            mma16816(ae[ni], A2eh, Be2l[ni][0], Be2l[ni][1]);
            mma16816(ao[ni], A2oh, Bo2l[ni][0], Bo2l[ni][1]);
            mma16816(ae[ni], A2el, Be2h[ni][0], Be2h[ni][1]);
            mma16816(ao[ni], A2ol, Bo2h[ni][0], Bo2h[ni][1]);
        }

        // ---- store: undo both permutations; 8 fully-coalesced STG.128 ----
        float* __restrict__ dst = out + (m0 + (size_t)b * 4) * 1024;
        #pragma unroll
        for (int half = 0; half < 2; half++) {
            int cbase = 16 * half + 4 * t;
            float* Ee = ae[half];  float* Eo = ae[half + 2];
            float* Oe = ao[half];  float* Oo = ao[half + 2];
            *reinterpret_cast<float4*>(&dst[(2 * g) * 32 + cbase]) =
                make_float4(Ee[0], Eo[0], Ee[1], Eo[1]);
            *reinterpret_cast<float4*>(&dst[(2 * g + 16) * 32 + cbase]) =
                make_float4(Ee[2], Eo[2], Ee[3], Eo[3]);
            *reinterpret_cast<float4*>(&dst[(2 * g + 1) * 32 + cbase]) =
                make_float4(Oe[0], Oo[0], Oe[1], Oo[1]);
            *reinterpret_cast<float4*>(&dst[(2 * g + 17) * 32 + cbase]) =
                make_float4(Oe[2], Oo[2], Oe[3], Oo[3]);
        }
    }
}

extern "C" void kernel_launch(void* const* d_in, const int* in_sizes, int n_in,
                              void* d_out, int out_size)
{
    const float* x = (const float*)d_in[0];   // [B, C, 32, 32] fp32
    const float* H = (const float*)d_in[1];   // [32, 32] fp32
    float* out = (float*)d_out;

    int nMat = in_sizes[0] / 1024;            // 65536 (divisible by 8)
    int blocks = nMat / 8;

    dct2d_mma_kernel<<<blocks, NTHREADS>>>(x, H, out, nMat);
}